// round 4
// baseline (speedup 1.0000x reference)
#include <cuda_runtime.h>

#define HIDDEN 256
#define WPB    4          // warps per block
#define PPW    4          // points per warp (2 packed pairs)
#define NPAIR  2

#define C11f 1.0989010989010990f
#define C12f 0.3296703296703297f
#define C33f 0.3846153846153846f

typedef unsigned long long ull;

__device__ __forceinline__ ull pack2(float lo, float hi) {
    ull r; asm("mov.b64 %0, {%1,%2};" : "=l"(r) : "f"(lo), "f"(hi)); return r;
}
__device__ __forceinline__ void unpack2(ull v, float& lo, float& hi) {
    asm("mov.b64 {%0,%1}, %2;" : "=f"(lo), "=f"(hi) : "l"(v));
}
__device__ __forceinline__ void fma2(ull& d, ull a, ull b) {
    asm("fma.rn.f32x2 %0, %1, %2, %0;" : "+l"(d) : "l"(a), "l"(b));
}

// sh[warp][vec][pair][k] : packed (p_even, p_odd) activation value for neuron k
__global__ __launch_bounds__(WPB * 32, 2)
void pinn_kernel(
    const float* __restrict__ X,
    const float* __restrict__ W1, const float* __restrict__ b1,
    const float* __restrict__ W2, const float* __restrict__ b2,
    const float* __restrict__ W3, const float* __restrict__ b3,
    const float* __restrict__ Wo, const float* __restrict__ bo,
    float* __restrict__ out, int npoints)
{
    __shared__ ull sh[WPB][3][NPAIR][HIDDEN];   // 48 KB

    const int warp  = threadIdx.x >> 5;
    const int lane  = threadIdx.x & 31;
    const int pbase = (blockIdx.x * WPB + warp) * PPW;

    // lane owns neurons {4*lane+t, t<4} and {128+4*lane+(t-4), t>=4}
    const int nA = 4 * lane;          // first group base
    const int nB = 128 + 4 * lane;    // second group base

    // packed accumulators / activations: [pair][neuron-slot]
    ull h2[NPAIR][8], ax2[NPAIR][8], ay2[NPAIR][8];

    // ---------------- layer 1 ----------------
    {
        float xs[PPW], ys[PPW];
#pragma unroll
        for (int p = 0; p < PPW; p++) {
            xs[p] = X[2 * (pbase + p)];
            ys[p] = X[2 * (pbase + p) + 1];
        }
        float4 wxA = *(const float4*)(W1 + nA);
        float4 wxB = *(const float4*)(W1 + nB);
        float4 wyA = *(const float4*)(W1 + HIDDEN + nA);
        float4 wyB = *(const float4*)(W1 + HIDDEN + nB);
        float4 bA  = *(const float4*)(b1 + nA);
        float4 bB  = *(const float4*)(b1 + nB);
        float wx[8] = {wxA.x,wxA.y,wxA.z,wxA.w, wxB.x,wxB.y,wxB.z,wxB.w};
        float wy[8] = {wyA.x,wyA.y,wyA.z,wyA.w, wyB.x,wyB.y,wyB.z,wyB.w};
        float bb[8] = {bA.x,bA.y,bA.z,bA.w, bB.x,bB.y,bB.z,bB.w};

        float h[PPW][8], ax[PPW][8], ay[PPW][8];
#pragma unroll
        for (int t = 0; t < 8; t++) {
#pragma unroll
            for (int p = 0; p < PPW; p++) {
                float zz = fmaf(xs[p], wx[t], fmaf(ys[p], wy[t], bb[t]));
                float hh = tanhf(zz);
                float g  = 1.f - hh * hh;
                h[p][t]  = hh;
                ax[p][t] = g * wx[t];
                ay[p][t] = g * wy[t];
            }
        }
#pragma unroll
        for (int pr = 0; pr < NPAIR; pr++) {
#pragma unroll
            for (int t = 0; t < 8; t++) {
                h2[pr][t]  = pack2(h[2*pr][t],  h[2*pr+1][t]);
                ax2[pr][t] = pack2(ax[2*pr][t], ax[2*pr+1][t]);
                ay2[pr][t] = pack2(ay[2*pr][t], ay[2*pr+1][t]);
            }
        }
    }

    // store packed activations to SMEM
#pragma unroll
    for (int pr = 0; pr < NPAIR; pr++) {
        *(ulonglong2*)(&sh[warp][0][pr][nA])     = make_ulonglong2(h2[pr][0], h2[pr][1]);
        *(ulonglong2*)(&sh[warp][0][pr][nA + 2]) = make_ulonglong2(h2[pr][2], h2[pr][3]);
        *(ulonglong2*)(&sh[warp][0][pr][nB])     = make_ulonglong2(h2[pr][4], h2[pr][5]);
        *(ulonglong2*)(&sh[warp][0][pr][nB + 2]) = make_ulonglong2(h2[pr][6], h2[pr][7]);
        *(ulonglong2*)(&sh[warp][1][pr][nA])     = make_ulonglong2(ax2[pr][0], ax2[pr][1]);
        *(ulonglong2*)(&sh[warp][1][pr][nA + 2]) = make_ulonglong2(ax2[pr][2], ax2[pr][3]);
        *(ulonglong2*)(&sh[warp][1][pr][nB])     = make_ulonglong2(ax2[pr][4], ax2[pr][5]);
        *(ulonglong2*)(&sh[warp][1][pr][nB + 2]) = make_ulonglong2(ax2[pr][6], ax2[pr][7]);
        *(ulonglong2*)(&sh[warp][2][pr][nA])     = make_ulonglong2(ay2[pr][0], ay2[pr][1]);
        *(ulonglong2*)(&sh[warp][2][pr][nA + 2]) = make_ulonglong2(ay2[pr][2], ay2[pr][3]);
        *(ulonglong2*)(&sh[warp][2][pr][nB])     = make_ulonglong2(ay2[pr][4], ay2[pr][5]);
        *(ulonglong2*)(&sh[warp][2][pr][nB + 2]) = make_ulonglong2(ay2[pr][6], ay2[pr][7]);
    }
    __syncwarp();

    // ---------------- layers 2 & 3 ----------------
#pragma unroll 1
    for (int layer = 0; layer < 2; layer++) {
        const float* W = (layer == 0) ? W2 : W3;
        const float* b = (layer == 0) ? b2 : b3;

        float4 bA4 = *(const float4*)(b + nA);
        float4 bB4 = *(const float4*)(b + nB);
        float bb[8] = {bA4.x,bA4.y,bA4.z,bA4.w, bB4.x,bB4.y,bB4.z,bB4.w};

        ull z2[NPAIR][8], zx2[NPAIR][8], zy2[NPAIR][8];
#pragma unroll
        for (int pr = 0; pr < NPAIR; pr++)
#pragma unroll
            for (int t = 0; t < 8; t++) {
                z2[pr][t]  = pack2(bb[t], bb[t]);
                zx2[pr][t] = 0ull;
                zy2[pr][t] = 0ull;
            }

#pragma unroll 1
        for (int k4 = 0; k4 < HIDDEN; k4 += 4) {
            // packed activations for k..k+3, each pair: broadcast LDS.128
            ulonglong2 hA[NPAIR], hB[NPAIR], axA[NPAIR], axB[NPAIR], ayA[NPAIR], ayB[NPAIR];
#pragma unroll
            for (int pr = 0; pr < NPAIR; pr++) {
                hA[pr]  = *(const ulonglong2*)(&sh[warp][0][pr][k4]);
                hB[pr]  = *(const ulonglong2*)(&sh[warp][0][pr][k4 + 2]);
                axA[pr] = *(const ulonglong2*)(&sh[warp][1][pr][k4]);
                axB[pr] = *(const ulonglong2*)(&sh[warp][1][pr][k4 + 2]);
                ayA[pr] = *(const ulonglong2*)(&sh[warp][2][pr][k4]);
                ayB[pr] = *(const ulonglong2*)(&sh[warp][2][pr][k4 + 2]);
            }
#pragma unroll
            for (int kk = 0; kk < 4; kk++) {
                const float* wrow = W + (size_t)(k4 + kk) * HIDDEN;
                float4 w0 = *(const float4*)(wrow + nA);   // dense: 512B/warp
                float4 w1 = *(const float4*)(wrow + nB);
                float wv[8] = {w0.x,w0.y,w0.z,w0.w, w1.x,w1.y,w1.z,w1.w};
                ull ww[8];
#pragma unroll
                for (int t = 0; t < 8; t++) ww[t] = pack2(wv[t], wv[t]);
#pragma unroll
                for (int pr = 0; pr < NPAIR; pr++) {
                    ull hk  = (kk == 0) ? hA[pr].x  : (kk == 1) ? hA[pr].y  : (kk == 2) ? hB[pr].x  : hB[pr].y;
                    ull axk = (kk == 0) ? axA[pr].x : (kk == 1) ? axA[pr].y : (kk == 2) ? axB[pr].x : axB[pr].y;
                    ull ayk = (kk == 0) ? ayA[pr].x : (kk == 1) ? ayA[pr].y : (kk == 2) ? ayB[pr].x : ayB[pr].y;
#pragma unroll
                    for (int t = 0; t < 8; t++) {
                        fma2(z2[pr][t],  hk,  ww[t]);
                        fma2(zx2[pr][t], axk, ww[t]);
                        fma2(zy2[pr][t], ayk, ww[t]);
                    }
                }
            }
        }

        __syncwarp();   // all lanes done reading previous layer's SMEM

        // activation: unpack, tanh, repack
#pragma unroll
        for (int pr = 0; pr < NPAIR; pr++) {
#pragma unroll
            for (int t = 0; t < 8; t++) {
                float za, zb, xa, xb, ya, yb;
                unpack2(z2[pr][t],  za, zb);
                unpack2(zx2[pr][t], xa, xb);
                unpack2(zy2[pr][t], ya, yb);
                float ha = tanhf(za), hb = tanhf(zb);
                float ga = 1.f - ha * ha, gb = 1.f - hb * hb;
                h2[pr][t]  = pack2(ha, hb);
                ax2[pr][t] = pack2(ga * xa, gb * xb);
                ay2[pr][t] = pack2(ga * ya, gb * yb);
            }
            *(ulonglong2*)(&sh[warp][0][pr][nA])     = make_ulonglong2(h2[pr][0], h2[pr][1]);
            *(ulonglong2*)(&sh[warp][0][pr][nA + 2]) = make_ulonglong2(h2[pr][2], h2[pr][3]);
            *(ulonglong2*)(&sh[warp][0][pr][nB])     = make_ulonglong2(h2[pr][4], h2[pr][5]);
            *(ulonglong2*)(&sh[warp][0][pr][nB + 2]) = make_ulonglong2(h2[pr][6], h2[pr][7]);
            *(ulonglong2*)(&sh[warp][1][pr][nA])     = make_ulonglong2(ax2[pr][0], ax2[pr][1]);
            *(ulonglong2*)(&sh[warp][1][pr][nA + 2]) = make_ulonglong2(ax2[pr][2], ax2[pr][3]);
            *(ulonglong2*)(&sh[warp][1][pr][nB])     = make_ulonglong2(ax2[pr][4], ax2[pr][5]);
            *(ulonglong2*)(&sh[warp][1][pr][nB + 2]) = make_ulonglong2(ax2[pr][6], ax2[pr][7]);
            *(ulonglong2*)(&sh[warp][2][pr][nA])     = make_ulonglong2(ay2[pr][0], ay2[pr][1]);
            *(ulonglong2*)(&sh[warp][2][pr][nA + 2]) = make_ulonglong2(ay2[pr][2], ay2[pr][3]);
            *(ulonglong2*)(&sh[warp][2][pr][nB])     = make_ulonglong2(ay2[pr][4], ay2[pr][5]);
            *(ulonglong2*)(&sh[warp][2][pr][nB + 2]) = make_ulonglong2(ay2[pr][6], ay2[pr][7]);
        }
        __syncwarp();
    }

    // ---------------- output layer (packed) ----------------
    ull pu2[NPAIR], pv2[NPAIR], pux2[NPAIR], pvx2[NPAIR], puy2[NPAIR], pvy2[NPAIR];
#pragma unroll
    for (int pr = 0; pr < NPAIR; pr++) {
        pu2[pr] = pv2[pr] = pux2[pr] = pvx2[pr] = puy2[pr] = pvy2[pr] = 0ull;
    }
    // Wo rows for owned neurons: [nA..nA+3] and [nB..nB+3], 2 floats per row
    float4 woA0 = *(const float4*)(Wo + 2 * nA);       // rows nA, nA+1
    float4 woA1 = *(const float4*)(Wo + 2 * nA + 4);   // rows nA+2, nA+3
    float4 woB0 = *(const float4*)(Wo + 2 * nB);
    float4 woB1 = *(const float4*)(Wo + 2 * nB + 4);
    float wo0[8] = {woA0.x, woA0.z, woA1.x, woA1.z, woB0.x, woB0.z, woB1.x, woB1.z};
    float wo1[8] = {woA0.y, woA0.w, woA1.y, woA1.w, woB0.y, woB0.w, woB1.y, woB1.w};

#pragma unroll
    for (int t = 0; t < 8; t++) {
        ull w0p = pack2(wo0[t], wo0[t]);
        ull w1p = pack2(wo1[t], wo1[t]);
#pragma unroll
        for (int pr = 0; pr < NPAIR; pr++) {
            fma2(pu2[pr],  h2[pr][t],  w0p);
            fma2(pv2[pr],  h2[pr][t],  w1p);
            fma2(pux2[pr], ax2[pr][t], w0p);
            fma2(pvx2[pr], ax2[pr][t], w1p);
            fma2(puy2[pr], ay2[pr][t], w0p);
            fma2(pvy2[pr], ay2[pr][t], w1p);
        }
    }

    // butterfly reduce packed sums (lane-wise fp32 adds on both halves)
#pragma unroll
    for (int off = 16; off > 0; off >>= 1) {
#pragma unroll
        for (int pr = 0; pr < NPAIR; pr++) {
            ull o;
            o = __shfl_xor_sync(0xFFFFFFFFu, pu2[pr],  off);
            { float a,bq,c,d; unpack2(pu2[pr],a,bq); unpack2(o,c,d); pu2[pr]=pack2(a+c,bq+d); }
            o = __shfl_xor_sync(0xFFFFFFFFu, pv2[pr],  off);
            { float a,bq,c,d; unpack2(pv2[pr],a,bq); unpack2(o,c,d); pv2[pr]=pack2(a+c,bq+d); }
            o = __shfl_xor_sync(0xFFFFFFFFu, pux2[pr], off);
            { float a,bq,c,d; unpack2(pux2[pr],a,bq); unpack2(o,c,d); pux2[pr]=pack2(a+c,bq+d); }
            o = __shfl_xor_sync(0xFFFFFFFFu, pvx2[pr], off);
            { float a,bq,c,d; unpack2(pvx2[pr],a,bq); unpack2(o,c,d); pvx2[pr]=pack2(a+c,bq+d); }
            o = __shfl_xor_sync(0xFFFFFFFFu, puy2[pr], off);
            { float a,bq,c,d; unpack2(puy2[pr],a,bq); unpack2(o,c,d); puy2[pr]=pack2(a+c,bq+d); }
            o = __shfl_xor_sync(0xFFFFFFFFu, pvy2[pr], off);
            { float a,bq,c,d; unpack2(pvy2[pr],a,bq); unpack2(o,c,d); pvy2[pr]=pack2(a+c,bq+d); }
        }
    }

    if (lane == 0) {
        float bo0 = bo[0], bo1 = bo[1];
#pragma unroll
        for (int pr = 0; pr < NPAIR; pr++) {
            float puA, puB, pvA, pvB, puxA, puxB, pvxA, pvxB, puyA, puyB, pvyA, pvyB;
            unpack2(pu2[pr],  puA,  puB);
            unpack2(pv2[pr],  pvA,  pvB);
            unpack2(pux2[pr], puxA, puxB);
            unpack2(pvx2[pr], pvxA, pvxB);
            unpack2(puy2[pr], puyA, puyB);
            unpack2(pvy2[pr], pvyA, pvyB);
#pragma unroll
            for (int s = 0; s < 2; s++) {
                int pt = pbase + 2 * pr + s;
                float u   = (s ? puB  : puA)  + bo0;
                float v   = (s ? pvB  : pvA)  + bo1;
                float u_x = (s ? puxB : puxA);
                float v_x = (s ? pvxB : pvxA);
                float u_y = (s ? puyB : puyA);
                float v_y = (s ? pvyB : pvyA);
                float u_xy = u_y + v_x;
                float sx  = C11f * u_x + C12f * v_y;
                float sy  = C12f * u_x + C11f * v_y;
                float sxy = C33f * u_xy;
                float sed = 0.5f * (sx * u_x + sy * v_y + sxy * u_xy);
                out[pt]               = u;
                out[npoints + pt]     = v;
                out[2 * npoints + pt] = sx;
                out[3 * npoints + pt] = sy;
                out[4 * npoints + pt] = sxy;
                out[5 * npoints + pt] = sed;
            }
        }
    }
}

extern "C" void kernel_launch(void* const* d_in, const int* in_sizes, int n_in,
                              void* d_out, int out_size)
{
    const float* X  = (const float*)d_in[0];
    const float* W1 = (const float*)d_in[1];
    const float* b1 = (const float*)d_in[2];
    const float* W2 = (const float*)d_in[3];
    const float* b2 = (const float*)d_in[4];
    const float* W3 = (const float*)d_in[5];
    const float* b3 = (const float*)d_in[6];
    const float* Wo = (const float*)d_in[7];
    const float* bo = (const float*)d_in[8];
    float* out = (float*)d_out;

    const int npoints = in_sizes[0] / 2;              // 262144
    const int ppb     = WPB * PPW;                    // 16 points/block
    const int nblocks = (npoints + ppb - 1) / ppb;    // 16384

    pinn_kernel<<<nblocks, WPB * 32>>>(X, W1, b1, W2, b2, W3, b3, Wo, bo,
                                       out, npoints);
}

// round 6
// speedup vs baseline: 2.0873x; 2.0873x over previous
#include <cuda_runtime.h>
#include <cuda_fp16.h>
#include <cstdint>

#define NPTS 262144
#define HID  256

#define C11f 1.0989010989010990f
#define C12f 0.3296703296703297f
#define C33f 0.3846153846153846f

// Weight fragments, frag-ordered: [L][tk16][split(hi/lo)][tn8(32)][t(32)] -> uint2 (2x b32 = 4 fp16)
__device__ __align__(16) uint2 g_Bf[2][16][2][32][32];   // 1 MB

// ---------------- SMEM layout (bytes) ----------------
// act arrays (frag order), 32768 B each:
//   0 h_hi, 1 h_lo, 2 ax_hi, 3 ax_lo, 4 ay_hi, 5 ay_lo
//   element addr within array: (tk*4+tm)*512 + (q>>1)*256 + t*8 + (q&1)*4   (b32 = 2 fp16, k-pair)
// B double buffer: 196608 + buf*16384 ; within: split*8192 + tn*256 + t*8 (uint2)
// out partials: 229376, float[6][64]
#define SM_BBUF 196608
#define SM_OUT  229376
#define SMEM_BYTES 230912

__device__ __forceinline__ uint32_t smem_u32(const void* p) {
    uint32_t a;
    asm("{ .reg .u64 t; cvta.to.shared.u64 t, %1; cvt.u32.u64 %0, t; }" : "=r"(a) : "l"(p));
    return a;
}

__device__ __forceinline__ void mma16816(float* c, uint32_t a0, uint32_t a1, uint32_t a2, uint32_t a3,
                                         uint32_t b0, uint32_t b1) {
    asm volatile(
        "mma.sync.aligned.m16n8k16.row.col.f32.f16.f16.f32 "
        "{%0,%1,%2,%3},{%4,%5,%6,%7},{%8,%9},{%0,%1,%2,%3};"
        : "+f"(c[0]), "+f"(c[1]), "+f"(c[2]), "+f"(c[3])
        : "r"(a0), "r"(a1), "r"(a2), "r"(a3), "r"(b0), "r"(b1));
}

__device__ __forceinline__ void split2(float v0, float v1, uint32_t& hi, uint32_t& lo) {
    __half h0 = __float2half_rn(v0), h1 = __float2half_rn(v1);
    __half l0 = __float2half_rn(v0 - __half2float(h0));
    __half l1 = __float2half_rn(v1 - __half2float(h1));
    __half2 hh = __halves2half2(h0, h1), ll = __halves2half2(l0, l1);
    hi = *(uint32_t*)&hh;
    lo = *(uint32_t*)&ll;
}

__device__ __forceinline__ void cpasync16(uint32_t dst, const void* src) {
    asm volatile("cp.async.cg.shared.global [%0], [%1], 16;" :: "r"(dst), "l"(src));
}
#define CP_COMMIT() asm volatile("cp.async.commit_group;" ::: "memory")
#define CP_WAIT0()  asm volatile("cp.async.wait_group 0;" ::: "memory")

// copy one 16KB B chunk (L, tk) into buffer buf
__device__ __forceinline__ void copyB(uint32_t sb, int L, int tk, int buf, int tid) {
    uint32_t dst = sb + SM_BBUF + buf * 16384 + tid * 16;
    const char* src = (const char*)&g_Bf[L][tk][0][0][0] + tid * 16;
#pragma unroll
    for (int i = 0; i < 4; i++) cpasync16(dst + i * 4096, src + i * 4096);
}

// ---------------- prep: weights -> fragment order, hi/lo split ----------------
__global__ void prep_weights(const float* __restrict__ W2, const float* __restrict__ W3) {
    int L = blockIdx.x >> 8;
    int k = blockIdx.x & 255;
    int n = threadIdx.x;
    float w = (L ? W3 : W2)[k * HID + n];
    __half hi = __float2half_rn(w);
    __half lo = __float2half_rn(w - __half2float(hi));
    int tk = k >> 4, kk = k & 15, tn = n >> 3;
    int t = (n & 7) * 4 + ((kk & 7) >> 1);
    int r = (kk >= 8) ? 1 : 0, hsel = kk & 1;
    __half* base = (__half*)g_Bf;
    int i0 = ((((L * 16 + tk) * 2 + 0) * 32 + tn) * 32 + t) * 4 + r * 2 + hsel;
    int i1 = ((((L * 16 + tk) * 2 + 1) * 32 + tn) * 32 + t) * 4 + r * 2 + hsel;
    base[i0] = hi;
    base[i1] = lo;
}

// ---------------- main fused kernel ----------------
__global__ void __launch_bounds__(256, 1)
pinn_mma(const float* __restrict__ X,
         const float* __restrict__ W1, const float* __restrict__ b1,
         const float* __restrict__ b2, const float* __restrict__ b3,
         const float* __restrict__ Wo, const float* __restrict__ bo,
         float* __restrict__ out)
{
    extern __shared__ char smem[];
    const uint32_t sb = smem_u32(smem);
    const int tid = threadIdx.x, w = tid >> 5, lane = tid & 31;
    const int tm = w >> 1, nh = w & 1;           // warp tile: rows tm*16.., n-half nh*128..
    const int pbase = blockIdx.x * 64;

    // zero output partials
    for (int i = tid; i < 384; i += 256) ((float*)(smem + SM_OUT))[i] = 0.f;

    // ---------------- layer 1 (elementwise, writes frag-ordered acts) ----------------
    {
        int m = tid & 63, nb = (tid >> 6) * 64;
        float2 xy = ((const float2*)X)[pbase + m];
        int tmm = m >> 4, mhi = ((m & 15) >= 8) ? 1 : 0, row = m & 7;
#pragma unroll 4
        for (int np = 0; np < 32; np++) {
            int n0 = nb + 2 * np;
            float wx0 = W1[n0], wx1 = W1[n0 + 1];
            float wy0 = W1[HID + n0], wy1 = W1[HID + n0 + 1];
            float z0 = fmaf(xy.x, wx0, fmaf(xy.y, wy0, b1[n0]));
            float z1 = fmaf(xy.x, wx1, fmaf(xy.y, wy1, b1[n0 + 1]));
            float h0 = tanhf(z0), h1 = tanhf(z1);
            float g0 = 1.f - h0 * h0, g1 = 1.f - h1 * h1;
            int kk = n0 & 15, tkp = n0 >> 4;
            int tp = row * 4 + ((kk & 7) >> 1);
            int q = mhi + ((kk >= 8) ? 2 : 0);
            int off = (tkp * 4 + tmm) * 512 + (q >> 1) * 256 + tp * 8 + (q & 1) * 4;
            uint32_t hi, lo;
            split2(h0, h1, hi, lo);
            *(uint32_t*)(smem + 0 * 32768 + off) = hi;
            *(uint32_t*)(smem + 1 * 32768 + off) = lo;
            split2(g0 * wx0, g1 * wx1, hi, lo);
            *(uint32_t*)(smem + 2 * 32768 + off) = hi;
            *(uint32_t*)(smem + 3 * 32768 + off) = lo;
            split2(g0 * wy0, g1 * wy1, hi, lo);
            *(uint32_t*)(smem + 4 * 32768 + off) = hi;
            *(uint32_t*)(smem + 5 * 32768 + off) = lo;
        }
    }
    __syncthreads();

    float g[16][4];   // tanh' at current layer, thread-local (c-frag aligned)

#pragma unroll 1
    for (int L = 0; L < 2; L++) {
        const float* bias = L ? b3 : b2;

        // ================= h pass =================
        {
            float acc[16][4];
#pragma unroll
            for (int j = 0; j < 16; j++)
                acc[j][0] = acc[j][1] = acc[j][2] = acc[j][3] = 0.f;

            copyB(sb, L, 0, 0, tid); CP_COMMIT(); CP_WAIT0(); __syncthreads();

#pragma unroll 1
            for (int tk = 0; tk < 16; tk++) {
                if (tk < 15) { copyB(sb, L, tk + 1, (tk + 1) & 1, tid); CP_COMMIT(); }
                const char* pa = smem + (tk * 4 + tm) * 512 + lane * 8;   // arr 0 = h_hi
                uint2 aH01 = *(const uint2*)(pa);
                uint2 aH23 = *(const uint2*)(pa + 256);
                uint2 aL01 = *(const uint2*)(pa + 32768);
                uint2 aL23 = *(const uint2*)(pa + 32768 + 256);
                const char* pb = smem + SM_BBUF + (tk & 1) * 16384 + lane * 8;
#pragma unroll
                for (int j = 0; j < 16; j++) {
                    int tn = nh * 16 + j;
                    uint2 bH = *(const uint2*)(pb + tn * 256);
                    uint2 bL = *(const uint2*)(pb + 8192 + tn * 256);
                    mma16816(acc[j], aH01.x, aH01.y, aH23.x, aH23.y, bH.x, bH.y);
                    mma16816(acc[j], aH01.x, aH01.y, aH23.x, aH23.y, bL.x, bL.y);
                    mma16816(acc[j], aL01.x, aL01.y, aL23.x, aL23.y, bH.x, bH.y);
                }
                CP_WAIT0(); __syncthreads();
            }

            // epilogue
            float pu0 = 0.f, pu1 = 0.f, pv0 = 0.f, pv1 = 0.f;
#pragma unroll
            for (int j = 0; j < 16; j++) {
                int n0 = nh * 128 + j * 8 + 2 * (lane & 3);
                float2 bb = ((const float2*)bias)[n0 >> 1];
                float h0 = tanhf(acc[j][0] + bb.x);
                float h1 = tanhf(acc[j][1] + bb.y);
                float h2 = tanhf(acc[j][2] + bb.x);
                float h3 = tanhf(acc[j][3] + bb.y);
                g[j][0] = 1.f - h0 * h0; g[j][1] = 1.f - h1 * h1;
                g[j][2] = 1.f - h2 * h2; g[j][3] = 1.f - h3 * h3;
                if (L == 0) {
                    int kk = n0 & 15, tkp = n0 >> 4;
                    int qk = (kk >= 8) ? 2 : 0;
                    int offL = (tkp * 4 + tm) * 512 + (qk >> 1) * 256 + lane * 8;
                    uint32_t hi, lo;
                    split2(h0, h1, hi, lo);
                    *(uint32_t*)(smem + 0 * 32768 + offL) = hi;
                    *(uint32_t*)(smem + 1 * 32768 + offL) = lo;
                    split2(h2, h3, hi, lo);
                    *(uint32_t*)(smem + 0 * 32768 + offL + 4) = hi;
                    *(uint32_t*)(smem + 1 * 32768 + offL + 4) = lo;
                } else {
                    float2 wo0 = ((const float2*)Wo)[n0];
                    float2 wo1 = ((const float2*)Wo)[n0 + 1];
                    pu0 += h0 * wo0.x + h1 * wo1.x;  pv0 += h0 * wo0.y + h1 * wo1.y;
                    pu1 += h2 * wo0.x + h3 * wo1.x;  pv1 += h2 * wo0.y + h3 * wo1.y;
                }
            }
            if (L == 1) {
                pu0 += __shfl_xor_sync(~0u, pu0, 1); pu0 += __shfl_xor_sync(~0u, pu0, 2);
                pv0 += __shfl_xor_sync(~0u, pv0, 1); pv0 += __shfl_xor_sync(~0u, pv0, 2);
                pu1 += __shfl_xor_sync(~0u, pu1, 1); pu1 += __shfl_xor_sync(~0u, pu1, 2);
                pv1 += __shfl_xor_sync(~0u, pv1, 1); pv1 += __shfl_xor_sync(~0u, pv1, 2);
                if ((lane & 3) == 0) {
                    int mlo = tm * 16 + (lane >> 2);
                    float* so = (float*)(smem + SM_OUT);
                    atomicAdd(&so[0 * 64 + mlo], pu0);
                    atomicAdd(&so[0 * 64 + mlo + 8], pu1);
                    atomicAdd(&so[1 * 64 + mlo], pv0);
                    atomicAdd(&so[1 * 64 + mlo + 8], pv1);
                }
            }
            __syncthreads();
        }

        // ================= tangent pass (ax & ay fused, shares B) =================
        {
            float accx[16][4], accy[16][4];
#pragma unroll
            for (int j = 0; j < 16; j++) {
                accx[j][0] = accx[j][1] = accx[j][2] = accx[j][3] = 0.f;
                accy[j][0] = accy[j][1] = accy[j][2] = accy[j][3] = 0.f;
            }

            copyB(sb, L, 0, 0, tid); CP_COMMIT(); CP_WAIT0(); __syncthreads();

#pragma unroll 1
            for (int tk = 0; tk < 16; tk++) {
                if (tk < 15) { copyB(sb, L, tk + 1, (tk + 1) & 1, tid); CP_COMMIT(); }
                const char* pa = smem + (tk * 4 + tm) * 512 + lane * 8;
                uint2 xH01 = *(const uint2*)(pa + 2 * 32768);
                uint2 xH23 = *(const uint2*)(pa + 2 * 32768 + 256);
                uint2 xL01 = *(const uint2*)(pa + 3 * 32768);
                uint2 xL23 = *(const uint2*)(pa + 3 * 32768 + 256);
                uint2 yH01 = *(const uint2*)(pa + 4 * 32768);
                uint2 yH23 = *(const uint2*)(pa + 4 * 32768 + 256);
                uint2 yL01 = *(const uint2*)(pa + 5 * 32768);
                uint2 yL23 = *(const uint2*)(pa + 5 * 32768 + 256);
                const char* pb = smem + SM_BBUF + (tk & 1) * 16384 + lane * 8;
#pragma unroll
                for (int j = 0; j < 16; j++) {
                    int tn = nh * 16 + j;
                    uint2 bH = *(const uint2*)(pb + tn * 256);
                    uint2 bL = *(const uint2*)(pb + 8192 + tn * 256);
                    mma16816(accx[j], xH01.x, xH01.y, xH23.x, xH23.y, bH.x, bH.y);
                    mma16816(accx[j], xH01.x, xH01.y, xH23.x, xH23.y, bL.x, bL.y);
                    mma16816(accx[j], xL01.x, xL01.y, xL23.x, xL23.y, bH.x, bH.y);
                    mma16816(accy[j], yH01.x, yH01.y, yH23.x, yH23.y, bH.x, bH.y);
                    mma16816(accy[j], yH01.x, yH01.y, yH23.x, yH23.y, bL.x, bL.y);
                    mma16816(accy[j], yL01.x, yL01.y, yL23.x, yL23.y, bH.x, bH.y);
                }
                CP_WAIT0(); __syncthreads();
            }

            // epilogue
            float px0 = 0.f, px1 = 0.f, qx0 = 0.f, qx1 = 0.f;
            float py0 = 0.f, py1 = 0.f, qy0 = 0.f, qy1 = 0.f;
#pragma unroll
            for (int j = 0; j < 16; j++) {
                int n0 = nh * 128 + j * 8 + 2 * (lane & 3);
                float ax0 = g[j][0] * accx[j][0], ax1 = g[j][1] * accx[j][1];
                float ax2 = g[j][2] * accx[j][2], ax3 = g[j][3] * accx[j][3];
                float ay0 = g[j][0] * accy[j][0], ay1 = g[j][1] * accy[j][1];
                float ay2 = g[j][2] * accy[j][2], ay3 = g[j][3] * accy[j][3];
                if (L == 0) {
                    int kk = n0 & 15, tkp = n0 >> 4;
                    int qk = (kk >= 8) ? 2 : 0;
                    int offL = (tkp * 4 + tm) * 512 + (qk >> 1) * 256 + lane * 8;
                    uint32_t hi, lo;
                    split2(ax0, ax1, hi, lo);
                    *(uint32_t*)(smem + 2 * 32768 + offL) = hi;
                    *(uint32_t*)(smem + 3 * 32768 + offL) = lo;
                    split2(ax2, ax3, hi, lo);
                    *(uint32_t*)(smem + 2 * 32768 + offL + 4) = hi;
                    *(uint32_t*)(smem + 3 * 32768 + offL + 4) = lo;
                    split2(ay0, ay1, hi, lo);
                    *(uint32_t*)(smem + 4 * 32768 + offL) = hi;
                    *(uint32_t*)(smem + 5 * 32768 + offL) = lo;
                    split2(ay2, ay3, hi, lo);
                    *(uint32_t*)(smem + 4 * 32768 + offL + 4) = hi;
                    *(uint32_t*)(smem + 5 * 32768 + offL + 4) = lo;
                } else {
                    float2 wo0 = ((const float2*)Wo)[n0];
                    float2 wo1 = ((const float2*)Wo)[n0 + 1];
                    px0 += ax0 * wo0.x + ax1 * wo1.x;  qx0 += ax0 * wo0.y + ax1 * wo1.y;
                    px1 += ax2 * wo0.x + ax3 * wo1.x;  qx1 += ax2 * wo0.y + ax3 * wo1.y;
                    py0 += ay0 * wo0.x + ay1 * wo1.x;  qy0 += ay0 * wo0.y + ay1 * wo1.y;
                    py1 += ay2 * wo0.x + ay3 * wo1.x;  qy1 += ay2 * wo0.y + ay3 * wo1.y;
                }
            }
            if (L == 1) {
#pragma unroll
                for (int off = 1; off <= 2; off <<= 1) {
                    px0 += __shfl_xor_sync(~0u, px0, off); px1 += __shfl_xor_sync(~0u, px1, off);
                    qx0 += __shfl_xor_sync(~0u, qx0, off); qx1 += __shfl_xor_sync(~0u, qx1, off);
                    py0 += __shfl_xor_sync(~0u, py0, off); py1 += __shfl_xor_sync(~0u, py1, off);
                    qy0 += __shfl_xor_sync(~0u, qy0, off); qy1 += __shfl_xor_sync(~0u, qy1, off);
                }
                if ((lane & 3) == 0) {
                    int mlo = tm * 16 + (lane >> 2);
                    float* so = (float*)(smem + SM_OUT);
                    atomicAdd(&so[2 * 64 + mlo], px0);  atomicAdd(&so[2 * 64 + mlo + 8], px1);
                    atomicAdd(&so[3 * 64 + mlo], qx0);  atomicAdd(&so[3 * 64 + mlo + 8], qx1);
                    atomicAdd(&so[4 * 64 + mlo], py0);  atomicAdd(&so[4 * 64 + mlo + 8], py1);
                    atomicAdd(&so[5 * 64 + mlo], qy0);  atomicAdd(&so[5 * 64 + mlo + 8], qy1);
                }
            }
            __syncthreads();
        }
    }

    // ---------------- final: stress transform ----------------
    if (tid < 64) {
        const float* so = (const float*)(smem + SM_OUT);
        float u   = so[0 * 64 + tid] + bo[0];
        float v   = so[1 * 64 + tid] + bo[1];
        float u_x = so[2 * 64 + tid], v_x = so[3 * 64 + tid];
        float u_y = so[4 * 64 + tid], v_y = so[5 * 64 + tid];
        float u_xy = u_y + v_x;
        float sx  = C11f * u_x + C12f * v_y;
        float sy  = C12f * u_x + C11f * v_y;
        float sxy = C33f * u_xy;
        float sed = 0.5f * (sx * u_x + sy * v_y + sxy * u_xy);
        int p = pbase + tid;
        out[p]            = u;
        out[NPTS + p]     = v;
        out[2 * NPTS + p] = sx;
        out[3 * NPTS + p] = sy;
        out[4 * NPTS + p] = sxy;
        out[5 * NPTS + p] = sed;
    }
}

// ---------------- launcher ----------------
extern "C" void kernel_launch(void* const* d_in, const int* in_sizes, int n_in,
                              void* d_out, int out_size)
{
    const float* X  = (const float*)d_in[0];
    const float* W1 = (const float*)d_in[1];
    const float* b1 = (const float*)d_in[2];
    const float* W2 = (const float*)d_in[3];
    const float* b2 = (const float*)d_in[4];
    const float* W3 = (const float*)d_in[5];
    const float* b3 = (const float*)d_in[6];
    const float* Wo = (const float*)d_in[7];
    const float* bo = (const float*)d_in[8];
    float* out = (float*)d_out;

    static bool attr_set = false;
    if (!attr_set) {
        cudaFuncSetAttribute(pinn_mma, cudaFuncAttributeMaxDynamicSharedMemorySize, SMEM_BYTES);
        attr_set = true;
    }

    prep_weights<<<512, 256>>>(W2, W3);
    pinn_mma<<<NPTS / 64, 256, SMEM_BYTES>>>(X, W1, b1, b2, b3, Wo, bo, out);
}

// round 7
// speedup vs baseline: 2.1209x; 1.0161x over previous
#include <cuda_runtime.h>
#include <cuda_fp16.h>
#include <cstdint>

#define NPTS 262144
#define HID  256
#define PPB  32
#define NTHREADS 384

#define C11f 1.0989010989010990f
#define C12f 0.3296703296703297f
#define C33f 0.3846153846153846f

// Weight fragments, frag-ordered: [L][tk16][split][tn8(32)][t(32)] -> uint2
__device__ __align__(16) uint2 g_Bf[2][16][2][32][32];   // 1 MB

// ---------------- SMEM layout ----------------
// ACT: 6 arrays x 16384 B: [vec(3)][split(2)]; within: (tk*2+tmm)*512 + (q>>1)*256 + t*8 + (q&1)*4
#define SM_ACT 0
#define SM_B   98304      // 2 buffers x 32768 (each = 2 tk chunks of 16KB)
#define SM_G   163840     // gtab float[32][264] padded = 33792 B
#define SM_OUT 197632     // float[6][32]
#define SMEM_BYTES 198400

__device__ __forceinline__ uint32_t smem_u32(const void* p) {
    uint32_t a;
    asm("{ .reg .u64 t; cvta.to.shared.u64 t, %1; cvt.u32.u64 %0, t; }" : "=r"(a) : "l"(p));
    return a;
}
__device__ __forceinline__ void mma16816(float* c, uint32_t a0, uint32_t a1, uint32_t a2, uint32_t a3,
                                         uint32_t b0, uint32_t b1) {
    asm volatile(
        "mma.sync.aligned.m16n8k16.row.col.f32.f16.f16.f32 "
        "{%0,%1,%2,%3},{%4,%5,%6,%7},{%8,%9},{%0,%1,%2,%3};"
        : "+f"(c[0]), "+f"(c[1]), "+f"(c[2]), "+f"(c[3])
        : "r"(a0), "r"(a1), "r"(a2), "r"(a3), "r"(b0), "r"(b1));
}
__device__ __forceinline__ void split2(float v0, float v1, uint32_t& hi, uint32_t& lo) {
    __half h0 = __float2half_rn(v0), h1 = __float2half_rn(v1);
    __half l0 = __float2half_rn(v0 - __half2float(h0));
    __half l1 = __float2half_rn(v1 - __half2float(h1));
    __half2 hh = __halves2half2(h0, h1), ll = __halves2half2(l0, l1);
    hi = *(uint32_t*)&hh;
    lo = *(uint32_t*)&ll;
}
__device__ __forceinline__ void cpasync16(uint32_t dst, const void* src) {
    asm volatile("cp.async.cg.shared.global [%0], [%1], 16;" :: "r"(dst), "l"(src));
}
#define CP_COMMIT() asm volatile("cp.async.commit_group;" ::: "memory")
#define CP_WAIT0()  asm volatile("cp.async.wait_group 0;" ::: "memory")

// copy one 32KB chunk (2 tk) of layer L into buffer buf
__device__ __forceinline__ void copyB2(char* smem, int L, int chunk, int buf, int tid) {
    if (tid < 256) {
        uint32_t dst = smem_u32(smem) + SM_B + buf * 32768 + tid * 16;
        const char* src = (const char*)g_Bf + L * 262144 + chunk * 32768 + tid * 16;
#pragma unroll
        for (int i = 0; i < 8; i++) cpasync16(dst + i * 4096, src + i * 4096);
    }
}

// ---------------- prep: weights -> fragment order, hi/lo split ----------------
__global__ void prep_weights(const float* __restrict__ W2, const float* __restrict__ W3) {
    int L = blockIdx.x >> 8;
    int k = blockIdx.x & 255;
    int n = threadIdx.x;
    float w = (L ? W3 : W2)[k * HID + n];
    __half hi = __float2half_rn(w);
    __half lo = __float2half_rn(w - __half2float(hi));
    int tk = k >> 4, kk = k & 15, tn = n >> 3;
    int t = (n & 7) * 4 + ((kk & 7) >> 1);
    int r = (kk >= 8) ? 1 : 0, hsel = kk & 1;
    __half* base = (__half*)g_Bf;
    int i0 = ((((L * 16 + tk) * 2 + 0) * 32 + tn) * 32 + t) * 4 + r * 2 + hsel;
    int i1 = ((((L * 16 + tk) * 2 + 1) * 32 + tn) * 32 + t) * 4 + r * 2 + hsel;
    base[i0] = hi;
    base[i1] = lo;
}

// ---------------- main fused kernel ----------------
__global__ void __launch_bounds__(NTHREADS, 1)
pinn_mma(const float* __restrict__ X,
         const float* __restrict__ W1, const float* __restrict__ b1,
         const float* __restrict__ b2, const float* __restrict__ b3,
         const float* __restrict__ Wo, const float* __restrict__ bo,
         float* __restrict__ out)
{
    extern __shared__ char smem[];
    const int tid = threadIdx.x, w = tid >> 5, lane = tid & 31;
    const int nh = w & 1, mt = w >> 1;     // mt 0..5
    const int vec = mt >> 1, tmm = mt & 1; // vec: 0=h 1=ax 2=ay ; tmm: m-tile within vec
    const int pbase = blockIdx.x * PPB;
    float* gtab = (float*)(smem + SM_G);
    float* so   = (float*)(smem + SM_OUT);

    if (tid < 192) so[tid] = 0.f;

    // ---------------- layer 1 (elementwise, frag-ordered acts) ----------------
    for (int idx = tid; idx < PPB * 128; idx += NTHREADS) {
        int m = idx >> 7, n0 = (idx & 127) * 2;
        float2 xy = ((const float2*)X)[pbase + m];
        float wx0 = W1[n0], wx1 = W1[n0 + 1];
        float wy0 = W1[HID + n0], wy1 = W1[HID + n0 + 1];
        float z0 = fmaf(xy.x, wx0, fmaf(xy.y, wy0, b1[n0]));
        float z1 = fmaf(xy.x, wx1, fmaf(xy.y, wy1, b1[n0 + 1]));
        float h0 = tanhf(z0), h1 = tanhf(z1);
        float g0 = 1.f - h0 * h0, g1 = 1.f - h1 * h1;
        int kk = n0 & 15, tkp = n0 >> 4;
        int t = (m & 7) * 4 + ((kk & 7) >> 1);
        int q = (((m & 15) >= 8) ? 1 : 0) + ((kk >= 8) ? 2 : 0);
        int off = (tkp * 2 + (m >> 4)) * 512 + (q >> 1) * 256 + t * 8 + (q & 1) * 4;
        uint32_t hi, lo;
        split2(h0, h1, hi, lo);
        *(uint32_t*)(smem + SM_ACT + 0 * 16384 + off) = hi;
        *(uint32_t*)(smem + SM_ACT + 1 * 16384 + off) = lo;
        split2(g0 * wx0, g1 * wx1, hi, lo);
        *(uint32_t*)(smem + SM_ACT + 2 * 16384 + off) = hi;
        *(uint32_t*)(smem + SM_ACT + 3 * 16384 + off) = lo;
        split2(g0 * wy0, g1 * wy1, hi, lo);
        *(uint32_t*)(smem + SM_ACT + 4 * 16384 + off) = hi;
        *(uint32_t*)(smem + SM_ACT + 5 * 16384 + off) = lo;
    }

    // prologue: prefetch L0 chunk0
    copyB2(smem, 0, 0, 0, tid);
    CP_COMMIT();

    const int p0 = tmm * 16 + (lane >> 2);   // this thread's first point row

#pragma unroll 1
    for (int L = 0; L < 2; L++) {
        const float* bias = L ? b3 : b2;
        float acc[16][4];
#pragma unroll
        for (int j = 0; j < 16; j++)
            acc[j][0] = acc[j][1] = acc[j][2] = acc[j][3] = 0.f;

        const char* abase = smem + SM_ACT + vec * 32768;   // hi array; lo at +16384

        // ---------------- mainloop: 8 iterations x 2 tk ----------------
#pragma unroll 1
        for (int it = 0; it < 8; it++) {
            CP_WAIT0();
            __syncthreads();
            if (it + 1 < 8) copyB2(smem, L, it + 1, (it + 1) & 1, tid);
            CP_COMMIT();
#pragma unroll
            for (int tkh = 0; tkh < 2; tkh++) {
                int tk = it * 2 + tkh;
                const char* pa = abase + (tk * 2 + tmm) * 512 + lane * 8;
                uint2 aH01 = *(const uint2*)pa;
                uint2 aH23 = *(const uint2*)(pa + 256);
                uint2 aL01 = *(const uint2*)(pa + 16384);
                uint2 aL23 = *(const uint2*)(pa + 16384 + 256);
                const char* pb = smem + SM_B + (it & 1) * 32768 + tkh * 16384 + lane * 8;
                if (vec == 0) {
#pragma unroll
                    for (int j = 0; j < 16; j++) {
                        int tn = nh * 16 + j;
                        uint2 bH = *(const uint2*)(pb + tn * 256);
                        uint2 bL = *(const uint2*)(pb + 8192 + tn * 256);
                        mma16816(acc[j], aH01.x, aH01.y, aH23.x, aH23.y, bH.x, bH.y);
                        mma16816(acc[j], aH01.x, aH01.y, aH23.x, aH23.y, bL.x, bL.y);
                        mma16816(acc[j], aL01.x, aL01.y, aL23.x, aL23.y, bH.x, bH.y);
                    }
                } else {
#pragma unroll
                    for (int j = 0; j < 16; j++) {
                        int tn = nh * 16 + j;
                        uint2 bH = *(const uint2*)(pb + tn * 256);
                        mma16816(acc[j], aH01.x, aH01.y, aH23.x, aH23.y, bH.x, bH.y);
                        mma16816(acc[j], aL01.x, aL01.y, aL23.x, aL23.y, bH.x, bH.y);
                    }
                }
            }
        }

        // prefetch next layer's first chunk (overlaps epilogue)
        if (L == 0) { copyB2(smem, 1, 0, 0, tid); CP_COMMIT(); }

        __syncthreads();   // all mainloop act reads complete

        // ---------------- epilogue phase 1: h warps ----------------
        if (vec == 0) {
            float pu0 = 0.f, pv0 = 0.f, pu1 = 0.f, pv1 = 0.f;
#pragma unroll
            for (int j = 0; j < 16; j++) {
                int n0 = nh * 128 + j * 8 + (lane & 3) * 2;
                float b0v = bias[n0], b1v = bias[n0 + 1];
                float h0 = tanhf(acc[j][0] + b0v);
                float h1 = tanhf(acc[j][1] + b1v);
                float h2 = tanhf(acc[j][2] + b0v);
                float h3 = tanhf(acc[j][3] + b1v);
                gtab[p0 * 264 + n0]           = 1.f - h0 * h0;
                gtab[p0 * 264 + n0 + 1]       = 1.f - h1 * h1;
                gtab[(p0 + 8) * 264 + n0]     = 1.f - h2 * h2;
                gtab[(p0 + 8) * 264 + n0 + 1] = 1.f - h3 * h3;
                if (L == 0) {
                    int off = ((n0 >> 4) * 2 + tmm) * 512 + (j & 1) * 256 + lane * 8;
                    uint32_t hi, lo;
                    split2(h0, h1, hi, lo);
                    *(uint32_t*)(smem + SM_ACT + 0 * 16384 + off) = hi;
                    *(uint32_t*)(smem + SM_ACT + 1 * 16384 + off) = lo;
                    split2(h2, h3, hi, lo);
                    *(uint32_t*)(smem + SM_ACT + 0 * 16384 + off + 4) = hi;
                    *(uint32_t*)(smem + SM_ACT + 1 * 16384 + off + 4) = lo;
                } else {
                    float4 wo = *(const float4*)(Wo + 2 * n0);
                    pu0 += h0 * wo.x + h1 * wo.z;  pv0 += h0 * wo.y + h1 * wo.w;
                    pu1 += h2 * wo.x + h3 * wo.z;  pv1 += h2 * wo.y + h3 * wo.w;
                }
            }
            if (L == 1) {
#pragma unroll
                for (int o = 1; o <= 2; o <<= 1) {
                    pu0 += __shfl_xor_sync(~0u, pu0, o);
                    pv0 += __shfl_xor_sync(~0u, pv0, o);
                    pu1 += __shfl_xor_sync(~0u, pu1, o);
                    pv1 += __shfl_xor_sync(~0u, pv1, o);
                }
                if ((lane & 3) == 0) {
                    atomicAdd(&so[0 * 32 + p0], pu0);
                    atomicAdd(&so[0 * 32 + p0 + 8], pu1);
                    atomicAdd(&so[1 * 32 + p0], pv0);
                    atomicAdd(&so[1 * 32 + p0 + 8], pv1);
                }
            }
        }
        __syncthreads();   // gtab ready

        // ---------------- epilogue phase 2: tangent warps ----------------
        if (vec > 0) {
            float px0 = 0.f, qx0 = 0.f, px1 = 0.f, qx1 = 0.f;
#pragma unroll
            for (int j = 0; j < 16; j++) {
                int n0 = nh * 128 + j * 8 + (lane & 3) * 2;
                float g0 = gtab[p0 * 264 + n0];
                float g1 = gtab[p0 * 264 + n0 + 1];
                float g2 = gtab[(p0 + 8) * 264 + n0];
                float g3 = gtab[(p0 + 8) * 264 + n0 + 1];
                float a0 = g0 * acc[j][0], a1 = g1 * acc[j][1];
                float a2 = g2 * acc[j][2], a3 = g3 * acc[j][3];
                if (L == 0) {
                    int off = ((n0 >> 4) * 2 + tmm) * 512 + (j & 1) * 256 + lane * 8;
                    uint32_t hi, lo;
                    split2(a0, a1, hi, lo);
                    *(uint32_t*)(smem + SM_ACT + (vec * 2 + 0) * 16384 + off) = hi;
                    *(uint32_t*)(smem + SM_ACT + (vec * 2 + 1) * 16384 + off) = lo;
                    split2(a2, a3, hi, lo);
                    *(uint32_t*)(smem + SM_ACT + (vec * 2 + 0) * 16384 + off + 4) = hi;
                    *(uint32_t*)(smem + SM_ACT + (vec * 2 + 1) * 16384 + off + 4) = lo;
                } else {
                    float4 wo = *(const float4*)(Wo + 2 * n0);
                    px0 += a0 * wo.x + a1 * wo.z;  qx0 += a0 * wo.y + a1 * wo.w;
                    px1 += a2 * wo.x + a3 * wo.z;  qx1 += a2 * wo.y + a3 * wo.w;
                }
            }
            if (L == 1) {
#pragma unroll
                for (int o = 1; o <= 2; o <<= 1) {
                    px0 += __shfl_xor_sync(~0u, px0, o);
                    qx0 += __shfl_xor_sync(~0u, qx0, o);
                    px1 += __shfl_xor_sync(~0u, px1, o);
                    qx1 += __shfl_xor_sync(~0u, qx1, o);
                }
                if ((lane & 3) == 0) {
                    atomicAdd(&so[(2 * vec) * 32 + p0], px0);
                    atomicAdd(&so[(2 * vec) * 32 + p0 + 8], px1);
                    atomicAdd(&so[(2 * vec + 1) * 32 + p0], qx0);
                    atomicAdd(&so[(2 * vec + 1) * 32 + p0 + 8], qx1);
                }
            }
        }
    }

    // ---------------- final: stress transform ----------------
    __syncthreads();
    if (tid < 32) {
        int p = tid;
        float u   = so[p] + bo[0];
        float v   = so[32 + p] + bo[1];
        float u_x = so[64 + p],  v_x = so[96 + p];
        float u_y = so[128 + p], v_y = so[160 + p];
        float u_xy = u_y + v_x;
        float sx  = C11f * u_x + C12f * v_y;
        float sy  = C12f * u_x + C11f * v_y;
        float sxy = C33f * u_xy;
        float sed = 0.5f * (sx * u_x + sy * v_y + sxy * u_xy);
        int pt = pbase + p;
        out[pt]            = u;
        out[NPTS + pt]     = v;
        out[2 * NPTS + pt] = sx;
        out[3 * NPTS + pt] = sy;
        out[4 * NPTS + pt] = sxy;
        out[5 * NPTS + pt] = sed;
    }
}

// ---------------- launcher ----------------
extern "C" void kernel_launch(void* const* d_in, const int* in_sizes, int n_in,
                              void* d_out, int out_size)
{
    const float* X  = (const float*)d_in[0];
    const float* W1 = (const float*)d_in[1];
    const float* b1 = (const float*)d_in[2];
    const float* W2 = (const float*)d_in[3];
    const float* b2 = (const float*)d_in[4];
    const float* W3 = (const float*)d_in[5];
    const float* b3 = (const float*)d_in[6];
    const float* Wo = (const float*)d_in[7];
    const float* bo = (const float*)d_in[8];
    float* out = (float*)d_out;

    static bool attr_set = false;
    if (!attr_set) {
        cudaFuncSetAttribute(pinn_mma, cudaFuncAttributeMaxDynamicSharedMemorySize, SMEM_BYTES);
        attr_set = true;
    }

    prep_weights<<<512, 256>>>(W2, W3);
    pinn_mma<<<NPTS / PPB, NTHREADS, SMEM_BYTES>>>(X, W1, b1, b2, b3, Wo, bo, out);
}

// round 8
// speedup vs baseline: 2.4918x; 1.1749x over previous
#include <cuda_runtime.h>
#include <cuda_fp16.h>
#include <cstdint>

#define NPTS 262144
#define HID  256

#define C11f 1.0989010989010990f
#define C12f 0.3296703296703297f
#define C33f 0.3846153846153846f

// Weight fragments, frag-ordered: [L][tk16][split(hi/lo)][tn8(32)][t(32)] -> uint2 (4 fp16)
__device__ __align__(16) uint2 g_Bf[2][16][2][32][32];   // 1 MB

// ---------------- SMEM layout (bytes) ----------------
// act arrays (frag order), 32768 B each:
//   0 h_hi, 1 h_lo, 2 ax_hi, 3 ax_lo, 4 ay_hi, 5 ay_lo
//   addr: (tk*4+tm)*512 + (q>>1)*256 + t*8 + (q&1)*4
// B buffers at SM_BBUF: two 16KB slots.
//   h-pass chunk (1 tk):   [split][tn][t]  split*8192 + tn*256 + t*8
//   tangent chunk (2 tk, hi only): [tkh][tn][t]  tkh*8192 + tn*256 + t*8
// out partials: SM_OUT, float[6][64]
#define SM_BBUF 196608
#define SM_OUT  229376
#define SMEM_BYTES 230912

__device__ __forceinline__ uint32_t smem_u32(const void* p) {
    uint32_t a;
    asm("{ .reg .u64 t; cvta.to.shared.u64 t, %1; cvt.u32.u64 %0, t; }" : "=r"(a) : "l"(p));
    return a;
}

__device__ __forceinline__ void mma16816(float* c, uint32_t a0, uint32_t a1, uint32_t a2, uint32_t a3,
                                         uint32_t b0, uint32_t b1) {
    asm volatile(
        "mma.sync.aligned.m16n8k16.row.col.f32.f16.f16.f32 "
        "{%0,%1,%2,%3},{%4,%5,%6,%7},{%8,%9},{%0,%1,%2,%3};"
        : "+f"(c[0]), "+f"(c[1]), "+f"(c[2]), "+f"(c[3])
        : "r"(a0), "r"(a1), "r"(a2), "r"(a3), "r"(b0), "r"(b1));
}

__device__ __forceinline__ void split2(float v0, float v1, uint32_t& hi, uint32_t& lo) {
    __half h0 = __float2half_rn(v0), h1 = __float2half_rn(v1);
    __half l0 = __float2half_rn(v0 - __half2float(h0));
    __half l1 = __float2half_rn(v1 - __half2float(h1));
    __half2 hh = __halves2half2(h0, h1), ll = __halves2half2(l0, l1);
    hi = *(uint32_t*)&hh;
    lo = *(uint32_t*)&ll;
}

__device__ __forceinline__ void cpasync16(uint32_t dst, const void* src) {
    asm volatile("cp.async.cg.shared.global [%0], [%1], 16;" :: "r"(dst), "l"(src));
}
#define CP_COMMIT() asm volatile("cp.async.commit_group;" ::: "memory")
#define CP_WAIT0()  asm volatile("cp.async.wait_group 0;" ::: "memory")

// h-pass: copy one full 16KB chunk (1 tk, hi+lo) into 16KB slot buf
__device__ __forceinline__ void copyH(uint32_t sb, int L, int tk, int buf, int tid) {
    uint32_t dst = sb + SM_BBUF + buf * 16384 + tid * 16;
    const char* src = (const char*)g_Bf + L * 262144 + tk * 16384 + tid * 16;
#pragma unroll
    for (int i = 0; i < 4; i++) cpasync16(dst + i * 4096, src + i * 4096);
}

// tangent pass: copy hi-only for 2 tk (2 x 8KB) into 16KB slot buf
__device__ __forceinline__ void copyT(uint32_t sb, int L, int chunk, int buf, int tid) {
    const char* base = (const char*)g_Bf + L * 262144;
#pragma unroll
    for (int i = 0; i < 4; i++) {
        int idx = i * 4096 + tid * 16;
        int tkh = idx >> 13;            // 0 or 1
        int off = idx & 8191;
        cpasync16(sb + SM_BBUF + buf * 16384 + idx,
                  base + (chunk * 2 + tkh) * 16384 + off);
    }
}

// ---------------- prep: weights -> fragment order, hi/lo split ----------------
__global__ void prep_weights(const float* __restrict__ W2, const float* __restrict__ W3) {
    int L = blockIdx.x >> 8;
    int k = blockIdx.x & 255;
    int n = threadIdx.x;
    float w = (L ? W3 : W2)[k * HID + n];
    __half hi = __float2half_rn(w);
    __half lo = __float2half_rn(w - __half2float(hi));
    int tk = k >> 4, kk = k & 15, tn = n >> 3;
    int t = (n & 7) * 4 + ((kk & 7) >> 1);
    int r = (kk >= 8) ? 1 : 0, hsel = kk & 1;
    __half* base = (__half*)g_Bf;
    int i0 = ((((L * 16 + tk) * 2 + 0) * 32 + tn) * 32 + t) * 4 + r * 2 + hsel;
    int i1 = ((((L * 16 + tk) * 2 + 1) * 32 + tn) * 32 + t) * 4 + r * 2 + hsel;
    base[i0] = hi;
    base[i1] = lo;
}

// ---------------- main fused kernel ----------------
__global__ void __launch_bounds__(256, 1)
pinn_mma(const float* __restrict__ X,
         const float* __restrict__ W1, const float* __restrict__ b1,
         const float* __restrict__ b2, const float* __restrict__ b3,
         const float* __restrict__ Wo, const float* __restrict__ bo,
         float* __restrict__ out)
{
    extern __shared__ char smem[];
    const uint32_t sb = smem_u32(smem);
    const int tid = threadIdx.x, w = tid >> 5, lane = tid & 31;
    const int tm = w >> 1, nh = w & 1;           // warp tile: rows tm*16.., n-half nh*128..
    const int pbase = blockIdx.x * 64;

    // zero output partials
    for (int i = tid; i < 384; i += 256) ((float*)(smem + SM_OUT))[i] = 0.f;

    // ---------------- layer 1 (elementwise, frag-ordered acts) ----------------
    {
        int m = tid & 63, nb = (tid >> 6) * 64;
        float2 xy = ((const float2*)X)[pbase + m];
        int tmm = m >> 4, mhi = ((m & 15) >= 8) ? 1 : 0, row = m & 7;
#pragma unroll 4
        for (int np = 0; np < 32; np++) {
            int n0 = nb + 2 * np;
            float wx0 = W1[n0], wx1 = W1[n0 + 1];
            float wy0 = W1[HID + n0], wy1 = W1[HID + n0 + 1];
            float z0 = fmaf(xy.x, wx0, fmaf(xy.y, wy0, b1[n0]));
            float z1 = fmaf(xy.x, wx1, fmaf(xy.y, wy1, b1[n0 + 1]));
            float h0 = tanhf(z0), h1 = tanhf(z1);
            float g0 = 1.f - h0 * h0, g1 = 1.f - h1 * h1;
            int kk = n0 & 15, tkp = n0 >> 4;
            int tp = row * 4 + ((kk & 7) >> 1);
            int q = mhi + ((kk >= 8) ? 2 : 0);
            int off = (tkp * 4 + tmm) * 512 + (q >> 1) * 256 + tp * 8 + (q & 1) * 4;
            uint32_t hi, lo;
            split2(h0, h1, hi, lo);
            *(uint32_t*)(smem + 0 * 32768 + off) = hi;
            *(uint32_t*)(smem + 1 * 32768 + off) = lo;
            split2(g0 * wx0, g1 * wx1, hi, lo);
            *(uint32_t*)(smem + 2 * 32768 + off) = hi;
            *(uint32_t*)(smem + 3 * 32768 + off) = lo;
            split2(g0 * wy0, g1 * wy1, hi, lo);
            *(uint32_t*)(smem + 4 * 32768 + off) = hi;
            *(uint32_t*)(smem + 5 * 32768 + off) = lo;
        }
    }

    // prologue: prefetch L0 h-chunk0
    copyH(sb, 0, 0, 0, tid);
    CP_COMMIT();

    float g[16][4];   // tanh' at current layer, thread-local

#pragma unroll 1
    for (int L = 0; L < 2; L++) {
        const float* bias = L ? b3 : b2;

        // ================= h pass (3-term) =================
        {
            float acc[16][4];
#pragma unroll
            for (int j = 0; j < 16; j++)
                acc[j][0] = acc[j][1] = acc[j][2] = acc[j][3] = 0.f;

#pragma unroll 1
            for (int tk = 0; tk < 16; tk++) {
                CP_WAIT0();
                __syncthreads();
                if (tk < 15) copyH(sb, L, tk + 1, (tk + 1) & 1, tid);
                else         copyT(sb, L, 0, 0, tid);        // tangent chunk0 into slot0
                CP_COMMIT();

                const char* pa = smem + (tk * 4 + tm) * 512 + lane * 8;   // h_hi
                uint2 aH01 = *(const uint2*)(pa);
                uint2 aH23 = *(const uint2*)(pa + 256);
                uint2 aL01 = *(const uint2*)(pa + 32768);
                uint2 aL23 = *(const uint2*)(pa + 32768 + 256);
                const char* pb = smem + SM_BBUF + (tk & 1) * 16384 + lane * 8;
#pragma unroll
                for (int j = 0; j < 16; j++) {
                    int tn = nh * 16 + j;
                    uint2 bH = *(const uint2*)(pb + tn * 256);
                    uint2 bL = *(const uint2*)(pb + 8192 + tn * 256);
                    mma16816(acc[j], aH01.x, aH01.y, aH23.x, aH23.y, bH.x, bH.y);
                    mma16816(acc[j], aH01.x, aH01.y, aH23.x, aH23.y, bL.x, bL.y);
                    mma16816(acc[j], aL01.x, aL01.y, aL23.x, aL23.y, bH.x, bH.y);
                }
            }
            __syncthreads();

            // epilogue
            float pu0 = 0.f, pu1 = 0.f, pv0 = 0.f, pv1 = 0.f;
#pragma unroll
            for (int j = 0; j < 16; j++) {
                int n0 = nh * 128 + j * 8 + 2 * (lane & 3);
                float2 bb = ((const float2*)bias)[n0 >> 1];
                float h0 = tanhf(acc[j][0] + bb.x);
                float h1 = tanhf(acc[j][1] + bb.y);
                float h2 = tanhf(acc[j][2] + bb.x);
                float h3 = tanhf(acc[j][3] + bb.y);
                g[j][0] = 1.f - h0 * h0; g[j][1] = 1.f - h1 * h1;
                g[j][2] = 1.f - h2 * h2; g[j][3] = 1.f - h3 * h3;
                if (L == 0) {
                    int kk = n0 & 15, tkp = n0 >> 4;
                    int qk = (kk >= 8) ? 2 : 0;
                    int offL = (tkp * 4 + tm) * 512 + (qk >> 1) * 256 + lane * 8;
                    uint32_t hi, lo;
                    split2(h0, h1, hi, lo);
                    *(uint32_t*)(smem + 0 * 32768 + offL) = hi;
                    *(uint32_t*)(smem + 1 * 32768 + offL) = lo;
                    split2(h2, h3, hi, lo);
                    *(uint32_t*)(smem + 0 * 32768 + offL + 4) = hi;
                    *(uint32_t*)(smem + 1 * 32768 + offL + 4) = lo;
                } else {
                    float2 wo0 = ((const float2*)Wo)[n0];
                    float2 wo1 = ((const float2*)Wo)[n0 + 1];
                    pu0 += h0 * wo0.x + h1 * wo1.x;  pv0 += h0 * wo0.y + h1 * wo1.y;
                    pu1 += h2 * wo0.x + h3 * wo1.x;  pv1 += h2 * wo0.y + h3 * wo1.y;
                }
            }
            if (L == 1) {
                pu0 += __shfl_xor_sync(~0u, pu0, 1); pu0 += __shfl_xor_sync(~0u, pu0, 2);
                pv0 += __shfl_xor_sync(~0u, pv0, 1); pv0 += __shfl_xor_sync(~0u, pv0, 2);
                pu1 += __shfl_xor_sync(~0u, pu1, 1); pu1 += __shfl_xor_sync(~0u, pu1, 2);
                pv1 += __shfl_xor_sync(~0u, pv1, 1); pv1 += __shfl_xor_sync(~0u, pv1, 2);
                if ((lane & 3) == 0) {
                    int mlo = tm * 16 + (lane >> 2);
                    float* so = (float*)(smem + SM_OUT);
                    atomicAdd(&so[0 * 64 + mlo], pu0);
                    atomicAdd(&so[0 * 64 + mlo + 8], pu1);
                    atomicAdd(&so[1 * 64 + mlo], pv0);
                    atomicAdd(&so[1 * 64 + mlo + 8], pv1);
                }
            }
            __syncthreads();
        }

        // ================= tangent pass (2-term, ax & ay fused, hi-only B) =================
        {
            float accx[16][4], accy[16][4];
#pragma unroll
            for (int j = 0; j < 16; j++) {
                accx[j][0] = accx[j][1] = accx[j][2] = accx[j][3] = 0.f;
                accy[j][0] = accy[j][1] = accy[j][2] = accy[j][3] = 0.f;
            }

#pragma unroll 1
            for (int it = 0; it < 8; it++) {
                CP_WAIT0();
                __syncthreads();
                if (it < 7)       copyT(sb, L, it + 1, (it + 1) & 1, tid);
                else if (L == 0)  copyH(sb, 1, 0, 0, tid);   // next layer h-chunk0
                CP_COMMIT();

#pragma unroll
                for (int tkh = 0; tkh < 2; tkh++) {
                    int tk = it * 2 + tkh;
                    const char* pa = smem + (tk * 4 + tm) * 512 + lane * 8;
                    uint2 xH01 = *(const uint2*)(pa + 2 * 32768);
                    uint2 xH23 = *(const uint2*)(pa + 2 * 32768 + 256);
                    uint2 xL01 = *(const uint2*)(pa + 3 * 32768);
                    uint2 xL23 = *(const uint2*)(pa + 3 * 32768 + 256);
                    uint2 yH01 = *(const uint2*)(pa + 4 * 32768);
                    uint2 yH23 = *(const uint2*)(pa + 4 * 32768 + 256);
                    uint2 yL01 = *(const uint2*)(pa + 5 * 32768);
                    uint2 yL23 = *(const uint2*)(pa + 5 * 32768 + 256);
                    const char* pb = smem + SM_BBUF + (it & 1) * 16384 + tkh * 8192 + lane * 8;
#pragma unroll
                    for (int j = 0; j < 16; j++) {
                        int tn = nh * 16 + j;
                        uint2 bH = *(const uint2*)(pb + tn * 256);
                        mma16816(accx[j], xH01.x, xH01.y, xH23.x, xH23.y, bH.x, bH.y);
                        mma16816(accx[j], xL01.x, xL01.y, xL23.x, xL23.y, bH.x, bH.y);
                        mma16816(accy[j], yH01.x, yH01.y, yH23.x, yH23.y, bH.x, bH.y);
                        mma16816(accy[j], yL01.x, yL01.y, yL23.x, yL23.y, bH.x, bH.y);
                    }
                }
            }
            __syncthreads();

            // epilogue
            float px0 = 0.f, px1 = 0.f, qx0 = 0.f, qx1 = 0.f;
            float py0 = 0.f, py1 = 0.f, qy0 = 0.f, qy1 = 0.f;
#pragma unroll
            for (int j = 0; j < 16; j++) {
                int n0 = nh * 128 + j * 8 + 2 * (lane & 3);
                float ax0 = g[j][0] * accx[j][0], ax1 = g[j][1] * accx[j][1];
                float ax2 = g[j][2] * accx[j][2], ax3 = g[j][3] * accx[j][3];
                float ay0 = g[j][0] * accy[j][0], ay1 = g[j][1] * accy[j][1];
                float ay2 = g[j][2] * accy[j][2], ay3 = g[j][3] * accy[j][3];
                if (L == 0) {
                    int kk = n0 & 15, tkp = n0 >> 4;
                    int qk = (kk >= 8) ? 2 : 0;
                    int offL = (tkp * 4 + tm) * 512 + (qk >> 1) * 256 + lane * 8;
                    uint32_t hi, lo;
                    split2(ax0, ax1, hi, lo);
                    *(uint32_t*)(smem + 2 * 32768 + offL) = hi;
                    *(uint32_t*)(smem + 3 * 32768 + offL) = lo;
                    split2(ax2, ax3, hi, lo);
                    *(uint32_t*)(smem + 2 * 32768 + offL + 4) = hi;
                    *(uint32_t*)(smem + 3 * 32768 + offL + 4) = lo;
                    split2(ay0, ay1, hi, lo);
                    *(uint32_t*)(smem + 4 * 32768 + offL) = hi;
                    *(uint32_t*)(smem + 5 * 32768 + offL) = lo;
                    split2(ay2, ay3, hi, lo);
                    *(uint32_t*)(smem + 4 * 32768 + offL + 4) = hi;
                    *(uint32_t*)(smem + 5 * 32768 + offL + 4) = lo;
                } else {
                    float2 wo0 = ((const float2*)Wo)[n0];
                    float2 wo1 = ((const float2*)Wo)[n0 + 1];
                    px0 += ax0 * wo0.x + ax1 * wo1.x;  qx0 += ax0 * wo0.y + ax1 * wo1.y;
                    px1 += ax2 * wo0.x + ax3 * wo1.x;  qx1 += ax2 * wo0.y + ax3 * wo1.y;
                    py0 += ay0 * wo0.x + ay1 * wo1.x;  qy0 += ay0 * wo0.y + ay1 * wo1.y;
                    py1 += ay2 * wo0.x + ay3 * wo1.x;  qy1 += ay2 * wo0.y + ay3 * wo1.y;
                }
            }
            if (L == 1) {
#pragma unroll
                for (int off = 1; off <= 2; off <<= 1) {
                    px0 += __shfl_xor_sync(~0u, px0, off); px1 += __shfl_xor_sync(~0u, px1, off);
                    qx0 += __shfl_xor_sync(~0u, qx0, off); qx1 += __shfl_xor_sync(~0u, qx1, off);
                    py0 += __shfl_xor_sync(~0u, py0, off); py1 += __shfl_xor_sync(~0u, py1, off);
                    qy0 += __shfl_xor_sync(~0u, qy0, off); qy1 += __shfl_xor_sync(~0u, qy1, off);
                }
                if ((lane & 3) == 0) {
                    int mlo = tm * 16 + (lane >> 2);
                    float* so = (float*)(smem + SM_OUT);
                    atomicAdd(&so[2 * 64 + mlo], px0);  atomicAdd(&so[2 * 64 + mlo + 8], px1);
                    atomicAdd(&so[3 * 64 + mlo], qx0);  atomicAdd(&so[3 * 64 + mlo + 8], qx1);
                    atomicAdd(&so[4 * 64 + mlo], py0);  atomicAdd(&so[4 * 64 + mlo + 8], py1);
                    atomicAdd(&so[5 * 64 + mlo], qy0);  atomicAdd(&so[5 * 64 + mlo + 8], qy1);
                }
            }
            __syncthreads();
        }
    }

    // ---------------- final: stress transform ----------------
    if (tid < 64) {
        const float* so = (const float*)(smem + SM_OUT);
        float u   = so[0 * 64 + tid] + bo[0];
        float v   = so[1 * 64 + tid] + bo[1];
        float u_x = so[2 * 64 + tid], v_x = so[3 * 64 + tid];
        float u_y = so[4 * 64 + tid], v_y = so[5 * 64 + tid];
        float u_xy = u_y + v_x;
        float sx  = C11f * u_x + C12f * v_y;
        float sy  = C12f * u_x + C11f * v_y;
        float sxy = C33f * u_xy;
        float sed = 0.5f * (sx * u_x + sy * v_y + sxy * u_xy);
        int p = pbase + tid;
        out[p]            = u;
        out[NPTS + p]     = v;
        out[2 * NPTS + p] = sx;
        out[3 * NPTS + p] = sy;
        out[4 * NPTS + p] = sxy;
        out[5 * NPTS + p] = sed;
    }
}

// ---------------- launcher ----------------
extern "C" void kernel_launch(void* const* d_in, const int* in_sizes, int n_in,
                              void* d_out, int out_size)
{
    const float* X  = (const float*)d_in[0];
    const float* W1 = (const float*)d_in[1];
    const float* b1 = (const float*)d_in[2];
    const float* W2 = (const float*)d_in[3];
    const float* b2 = (const float*)d_in[4];
    const float* W3 = (const float*)d_in[5];
    const float* b3 = (const float*)d_in[6];
    const float* Wo = (const float*)d_in[7];
    const float* bo = (const float*)d_in[8];
    float* out = (float*)d_out;

    static bool attr_set = false;
    if (!attr_set) {
        cudaFuncSetAttribute(pinn_mma, cudaFuncAttributeMaxDynamicSharedMemorySize, SMEM_BYTES);
        attr_set = true;
    }

    prep_weights<<<512, 256>>>(W2, W3);
    pinn_mma<<<NPTS / 64, 256, SMEM_BYTES>>>(X, W1, b1, b2, b3, Wo, bo, out);
}